// round 1
// baseline (speedup 1.0000x reference)
#include <cuda_runtime.h>

#define MAXN 50000
#define MAXE 800000

// -------- scratch (device globals; no allocation) --------
__device__ float g_prop_src[MAXN * 128];   // [N,128]
__device__ float g_a_src[MAXN * 8];        // [N,8]
__device__ float g_a_dst[MAXN * 8];        // [N,8]
__device__ float g_att[MAXE * 8];          // [E,8]  relu'd logits
__device__ int   g_count[MAXN + 1];
__device__ int   g_rowstart[MAXN + 1];
__device__ int   g_cursor[MAXN];
__device__ int   g_perm[MAXE];

// ============================================================
// K0: zero histogram
// ============================================================
__global__ void zero_count_kernel(int n) {
    int i = blockIdx.x * blockDim.x + threadIdx.x;
    if (i <= n) g_count[i] = 0;
}

// ============================================================
// K1: per-node GEMMs.
//   prop_src -> g_prop_src, prop_dst -> out (residual base),
//   a_src -> g_a_src, a_dst -> g_a_dst.
// Tile of 32 nodes per block, 128 threads. feat tile in smem.
// ============================================================
__global__ __launch_bounds__(128) void node_kernel(
    const float* __restrict__ feat,
    const float* __restrict__ wps, const float* __restrict__ bps,
    const float* __restrict__ wpd, const float* __restrict__ bpd,
    const float* __restrict__ was0, const float* __restrict__ was1,
    const float* __restrict__ wad0, const float* __restrict__ wad1,
    float* __restrict__ out, int n)
{
    __shared__ float sf[32 * 128];   // feat tile, later reused as relu(hidden)
    const int tid = threadIdx.x;
    const int n0 = blockIdx.x * 32;

    // load feat tile (zero-pad tail)
    for (int idx = tid; idx < 32 * 128; idx += 128) {
        int node = n0 + (idx >> 7);
        sf[idx] = (node < n) ? feat[n0 * 128 + idx] : 0.f;
    }
    __syncthreads();

    // ---- fused prop_src / prop_dst: thread = output column ----
    float acc1[32], acc2[32];
    #pragma unroll
    for (int i = 0; i < 32; i++) { acc1[i] = 0.f; acc2[i] = 0.f; }
    for (int k = 0; k < 128; k++) {
        float w1 = wps[k * 128 + tid];
        float w2 = wpd[k * 128 + tid];
        #pragma unroll
        for (int i = 0; i < 32; i++) {
            float f = sf[i * 128 + k];
            acc1[i] = fmaf(f, w1, acc1[i]);
            acc2[i] = fmaf(f, w2, acc2[i]);
        }
    }
    {
        float bs = bps[tid], bd = bpd[tid];
        #pragma unroll
        for (int i = 0; i < 32; i++) {
            int node = n0 + i;
            if (node < n) {
                g_prop_src[node * 128 + tid] = acc1[i] + bs;
                out[node * 128 + tid]        = acc2[i] + bd;
            }
        }
    }

    // ---- attention layer 0: threads 0..63 -> w_att_src0 col, 64..127 -> w_att_dst0 col ----
    const float* W0 = (tid < 64) ? was0 : wad0;
    const int col = tid & 63;
    float acc[32];
    #pragma unroll
    for (int i = 0; i < 32; i++) acc[i] = 0.f;
    for (int k = 0; k < 128; k++) {
        float w = W0[k * 64 + col];
        #pragma unroll
        for (int i = 0; i < 32; i++)
            acc[i] = fmaf(sf[i * 128 + k], w, acc[i]);
    }
    __syncthreads();   // all reads of feat tile done
    #pragma unroll
    for (int i = 0; i < 32; i++)
        sf[i * 128 + tid] = fmaxf(acc[i], 0.f);   // hidden: cols 0..63 src, 64..127 dst
    __syncthreads();

    // ---- attention layer 1: 32 nodes x (2 mats x 8 heads) = 512 outputs ----
    #pragma unroll
    for (int q = 0; q < 4; q++) {
        int o   = q * 128 + tid;
        int i   = o >> 4;
        int rem = o & 15;
        int mat = rem >> 3;     // 0 = src, 1 = dst
        int h   = rem & 7;
        const float* W1 = mat ? wad1 : was1;
        float s = 0.f;
        #pragma unroll
        for (int t = 0; t < 64; t++)
            s = fmaf(sf[i * 128 + mat * 64 + t], W1[t * 8 + h], s);
        int node = n0 + i;
        if (node < n) {
            if (mat == 0) g_a_src[node * 8 + h] = s;
            else          g_a_dst[node * 8 + h] = s;
        }
    }
}

// ============================================================
// K2: per-edge attention logits + degree histogram.
//   att[e][h] = relu( a_edge_mlp(feat_edge[e])[h] + a_src[src][h] + a_dst[dst][h] )
// ============================================================
__global__ __launch_bounds__(256) void edge_att_kernel(
    const float* __restrict__ feat_edge,
    const int* __restrict__ src, const int* __restrict__ dst,
    const float* __restrict__ we0, const float* __restrict__ we1,
    int e)
{
    __shared__ float sw0[8 * 64];
    __shared__ float sw1[64 * 8];
    const int tid = threadIdx.x;
    for (int i = tid; i < 512; i += 256) { sw0[i] = we0[i]; sw1[i] = we1[i]; }
    __syncthreads();

    int eid = blockIdx.x * 256 + tid;
    if (eid >= e) return;

    float fe[8];
    {
        const float4* fp = (const float4*)(feat_edge + (size_t)eid * 8);
        float4 f0 = fp[0], f1 = fp[1];
        fe[0] = f0.x; fe[1] = f0.y; fe[2] = f0.z; fe[3] = f0.w;
        fe[4] = f1.x; fe[5] = f1.y; fe[6] = f1.z; fe[7] = f1.w;
    }

    float a[8];
    #pragma unroll
    for (int h = 0; h < 8; h++) a[h] = 0.f;
    #pragma unroll 4
    for (int t = 0; t < 64; t++) {
        float hv = 0.f;
        #pragma unroll
        for (int k = 0; k < 8; k++) hv = fmaf(fe[k], sw0[k * 64 + t], hv);
        hv = fmaxf(hv, 0.f);
        #pragma unroll
        for (int h = 0; h < 8; h++) a[h] = fmaf(hv, sw1[t * 8 + h], a[h]);
    }

    int s = src[eid], d = dst[eid];
    const float4* as = (const float4*)(g_a_src + (size_t)s * 8);
    const float4* ad = (const float4*)(g_a_dst + (size_t)d * 8);
    float4 s0 = as[0], s1 = as[1];
    float4 d0 = ad[0], d1 = ad[1];

    float4 o0, o1;
    o0.x = fmaxf(a[0] + s0.x + d0.x, 0.f);
    o0.y = fmaxf(a[1] + s0.y + d0.y, 0.f);
    o0.z = fmaxf(a[2] + s0.z + d0.z, 0.f);
    o0.w = fmaxf(a[3] + s0.w + d0.w, 0.f);
    o1.x = fmaxf(a[4] + s1.x + d1.x, 0.f);
    o1.y = fmaxf(a[5] + s1.y + d1.y, 0.f);
    o1.z = fmaxf(a[6] + s1.z + d1.z, 0.f);
    o1.w = fmaxf(a[7] + s1.w + d1.w, 0.f);
    float4* op = (float4*)(g_att + (size_t)eid * 8);
    op[0] = o0; op[1] = o1;

    atomicAdd(&g_count[d], 1);
}

// ============================================================
// K3: exclusive scan of degree histogram (single block, chunked)
// ============================================================
__global__ __launch_bounds__(1024) void scan_kernel(int n) {
    __shared__ int buf[1024];
    const int tid = threadIdx.x;
    int off = 0;   // identical running prefix on every thread
    for (int base = 0; base < n; base += 1024) {
        int i = base + tid;
        int v = (i < n) ? g_count[i] : 0;
        buf[tid] = v;
        __syncthreads();
        #pragma unroll
        for (int s = 1; s < 1024; s <<= 1) {
            int add = (tid >= s) ? buf[tid - s] : 0;
            __syncthreads();
            buf[tid] += add;
            __syncthreads();
        }
        int incl = buf[tid];
        int tot  = buf[1023];
        int excl = incl - v;
        if (i < n) {
            g_rowstart[i] = off + excl;
            g_cursor[i]   = off + excl;
        }
        off += tot;
        __syncthreads();
    }
    if (tid == 0) g_rowstart[n] = off;
}

// ============================================================
// K3b: scatter edge ids into CSR order
// ============================================================
__global__ void scatter_kernel(const int* __restrict__ dst, int e) {
    int i = blockIdx.x * blockDim.x + threadIdx.x;
    if (i < e) {
        int d = dst[i];
        int pos = atomicAdd(&g_cursor[d], 1);
        g_perm[pos] = i;
    }
}

// ============================================================
// K4: per-destination softmax + weighted aggregation.
// One block (128 threads) per destination node; thread t owns
// output component t (head h = t>>4). out already holds prop_dst.
// ============================================================
__global__ __launch_bounds__(128) void aggregate_kernel(
    const int* __restrict__ src, float* __restrict__ out, int n)
{
    const int d = blockIdx.x;
    const int beg = g_rowstart[d];
    const int end = g_rowstart[d + 1];
    __shared__ float s_m[8], s_inv[8];
    const int t = threadIdx.x;

    if (t < 8) {
        float m = 0.f;   // att >= 0, so 0 is the exact identity for segment max
        for (int i = beg; i < end; i++)
            m = fmaxf(m, g_att[(size_t)g_perm[i] * 8 + t]);
        float ss = 0.f;
        for (int i = beg; i < end; i++)
            ss += __expf(g_att[(size_t)g_perm[i] * 8 + t] - m);
        s_m[t]   = m;
        s_inv[t] = 1.f / fmaxf(ss, 1e-16f);
    }
    __syncthreads();

    const int h = t >> 4;
    const float m = s_m[h], inv = s_inv[h];
    float acc = 0.f;
    for (int i = beg; i < end; i++) {
        int eid = g_perm[i];
        float al = __expf(g_att[(size_t)eid * 8 + h] - m) * inv;
        int s = src[eid];
        acc = fmaf(g_prop_src[(size_t)s * 128 + t], al, acc);
    }
    out[(size_t)d * 128 + t] += acc;
}

// ============================================================
// launch
// ============================================================
extern "C" void kernel_launch(void* const* d_in, const int* in_sizes, int n_in,
                              void* d_out, int out_size)
{
    const float* feat      = (const float*)d_in[0];
    const float* feat_edge = (const float*)d_in[1];
    const int*   src       = (const int*)  d_in[2];
    const int*   dst       = (const int*)  d_in[3];
    const float* was0      = (const float*)d_in[4];
    const float* was1      = (const float*)d_in[5];
    const float* wad0      = (const float*)d_in[6];
    const float* wad1      = (const float*)d_in[7];
    const float* we0       = (const float*)d_in[8];
    const float* we1       = (const float*)d_in[9];
    const float* wps       = (const float*)d_in[10];
    const float* bps       = (const float*)d_in[11];
    const float* wpd       = (const float*)d_in[12];
    const float* bpd       = (const float*)d_in[13];
    float* out = (float*)d_out;

    int n = in_sizes[0] / 128;
    int e = in_sizes[2];

    zero_count_kernel<<<(n + 256) / 256, 256>>>(n);
    node_kernel<<<(n + 31) / 32, 128>>>(feat, wps, bps, wpd, bpd,
                                        was0, was1, wad0, wad1, out, n);
    edge_att_kernel<<<(e + 255) / 256, 256>>>(feat_edge, src, dst, we0, we1, e);
    scan_kernel<<<1, 1024>>>(n);
    scatter_kernel<<<(e + 255) / 256, 256>>>(dst, e);
    aggregate_kernel<<<n, 128>>>(src, out, n);
}

// round 2
// speedup vs baseline: 1.4915x; 1.4915x over previous
#include <cuda_runtime.h>

#define MAXN 50000
#define MAXE 800000
#define CAP  512   // max staged edges per destination (Poisson(16) max ~45; huge margin)

// -------- scratch (device globals; no allocation) --------
__device__ float g_prop_src[MAXN * 128];   // [N,128]
__device__ float g_a_src[MAXN * 8];        // [N,8]
__device__ float g_a_dst[MAXN * 8];        // [N,8]
__device__ float g_att[MAXE * 8];          // [E,8]  relu'd logits
__device__ int   g_count[MAXN + 1];
__device__ int   g_rowstart[MAXN + 1];
__device__ int   g_cursor[MAXN];
__device__ int   g_perm[MAXE];
__device__ int   g_blocksum[64];
__device__ int   g_blockoff[64];

// -------- f32x2 packed-FMA helpers (FFMA2; PTX-only on Blackwell) --------
__device__ __forceinline__ void ffma2(unsigned long long& d,
                                      unsigned long long a,
                                      unsigned long long b) {
    asm("fma.rn.f32x2 %0, %1, %2, %0;" : "+l"(d) : "l"(a), "l"(b));
}
__device__ __forceinline__ unsigned long long pack2(float x) {
    unsigned long long r;
    asm("mov.b64 %0, {%1, %1};" : "=l"(r) : "f"(x));
    return r;
}
__device__ __forceinline__ void unpack2(unsigned long long v, float& lo, float& hi) {
    asm("mov.b64 {%0, %1}, %2;" : "=f"(lo), "=f"(hi) : "l"(v));
}

// ============================================================
// K0: zero histogram
// ============================================================
__global__ void zero_count_kernel(int n) {
    int i = blockIdx.x * blockDim.x + threadIdx.x;
    if (i <= n) g_count[i] = 0;
}

// ============================================================
// K1: per-node GEMMs (FFMA2 path).
// feat tile stored transposed: sft[k][i], pitch 34 floats.
// ============================================================
__global__ __launch_bounds__(128) void node_kernel(
    const float* __restrict__ feat,
    const float* __restrict__ wps, const float* __restrict__ bps,
    const float* __restrict__ wpd, const float* __restrict__ bpd,
    const float* __restrict__ was0, const float* __restrict__ was1,
    const float* __restrict__ wad0, const float* __restrict__ wad1,
    float* __restrict__ out, int n)
{
    __shared__ float sft[128 * 34];   // [k][i] padded; later reused as hidden [col][i]
    const int tid = threadIdx.x;
    const int n0 = blockIdx.x * 32;

    // load transposed feat tile: thread tid = feature k, iterate nodes
    #pragma unroll 4
    for (int i = 0; i < 32; i++) {
        int node = n0 + i;
        float v = (node < n) ? feat[(size_t)node * 128 + tid] : 0.f;
        sft[tid * 34 + i] = v;
    }
    __syncthreads();

    // ---- fused prop_src / prop_dst: thread = output column tid ----
    {
        unsigned long long acc1[16], acc2[16];
        #pragma unroll
        for (int j = 0; j < 16; j++) { acc1[j] = 0ull; acc2[j] = 0ull; }
        #pragma unroll 2
        for (int k = 0; k < 128; k++) {
            unsigned long long w1 = pack2(wps[k * 128 + tid]);
            unsigned long long w2 = pack2(wpd[k * 128 + tid]);
            const unsigned long long* fp =
                (const unsigned long long*)&sft[k * 34];
            #pragma unroll
            for (int j = 0; j < 16; j++) {
                unsigned long long f = fp[j];
                ffma2(acc1[j], f, w1);
                ffma2(acc2[j], f, w2);
            }
        }
        float bs = bps[tid], bd = bpd[tid];
        #pragma unroll
        for (int j = 0; j < 16; j++) {
            float l1, h1, l2, h2;
            unpack2(acc1[j], l1, h1);
            unpack2(acc2[j], l2, h2);
            int na = n0 + 2 * j, nb2 = na + 1;
            if (na < n) {
                g_prop_src[(size_t)na * 128 + tid] = l1 + bs;
                out[(size_t)na * 128 + tid]        = l2 + bd;
            }
            if (nb2 < n) {
                g_prop_src[(size_t)nb2 * 128 + tid] = h1 + bs;
                out[(size_t)nb2 * 128 + tid]        = h2 + bd;
            }
        }
    }

    // ---- attention layer 0: threads 0..63 src cols, 64..127 dst cols ----
    {
        const float* W0 = (tid < 64) ? was0 : wad0;
        const int col = tid & 63;
        unsigned long long acc[16];
        #pragma unroll
        for (int j = 0; j < 16; j++) acc[j] = 0ull;
        #pragma unroll 2
        for (int k = 0; k < 128; k++) {
            unsigned long long w = pack2(W0[k * 64 + col]);
            const unsigned long long* fp =
                (const unsigned long long*)&sft[k * 34];
            #pragma unroll
            for (int j = 0; j < 16; j++) ffma2(acc[j], fp[j], w);
        }
        __syncthreads();   // all reads of feat tile done
        #pragma unroll
        for (int j = 0; j < 16; j++) {
            float lo, hi;
            unpack2(acc[j], lo, hi);
            sft[tid * 34 + 2 * j]     = fmaxf(lo, 0.f);
            sft[tid * 34 + 2 * j + 1] = fmaxf(hi, 0.f);
        }
        __syncthreads();
    }

    // ---- attention layer 1: 32 nodes x (2 mats x 8 heads) = 512 outputs ----
    #pragma unroll
    for (int q = 0; q < 4; q++) {
        int o   = q * 128 + tid;
        int i   = o >> 4;
        int rem = o & 15;
        int mat = rem >> 3;
        int h   = rem & 7;
        const float* W1 = mat ? wad1 : was1;
        float s = 0.f;
        #pragma unroll
        for (int t = 0; t < 64; t++)
            s = fmaf(sft[(mat * 64 + t) * 34 + i], W1[t * 8 + h], s);
        int node = n0 + i;
        if (node < n) {
            if (mat == 0) g_a_src[node * 8 + h] = s;
            else          g_a_dst[node * 8 + h] = s;
        }
    }
}

// ============================================================
// K2: per-edge attention logits + degree histogram.
// ============================================================
__global__ __launch_bounds__(256) void edge_att_kernel(
    const float* __restrict__ feat_edge,
    const int* __restrict__ src, const int* __restrict__ dst,
    const float* __restrict__ we0, const float* __restrict__ we1,
    int e)
{
    __shared__ float sw0[8 * 64];
    __shared__ float sw1[64 * 8];
    const int tid = threadIdx.x;
    for (int i = tid; i < 512; i += 256) { sw0[i] = we0[i]; sw1[i] = we1[i]; }
    __syncthreads();

    int eid = blockIdx.x * 256 + tid;
    if (eid >= e) return;

    float fe[8];
    {
        const float4* fp = (const float4*)(feat_edge + (size_t)eid * 8);
        float4 f0 = fp[0], f1 = fp[1];
        fe[0] = f0.x; fe[1] = f0.y; fe[2] = f0.z; fe[3] = f0.w;
        fe[4] = f1.x; fe[5] = f1.y; fe[6] = f1.z; fe[7] = f1.w;
    }

    float a[8];
    #pragma unroll
    for (int h = 0; h < 8; h++) a[h] = 0.f;
    #pragma unroll 4
    for (int t = 0; t < 64; t++) {
        float hv = 0.f;
        #pragma unroll
        for (int k = 0; k < 8; k++) hv = fmaf(fe[k], sw0[k * 64 + t], hv);
        hv = fmaxf(hv, 0.f);
        #pragma unroll
        for (int h = 0; h < 8; h++) a[h] = fmaf(hv, sw1[t * 8 + h], a[h]);
    }

    int s = src[eid], d = dst[eid];
    const float4* as = (const float4*)(g_a_src + (size_t)s * 8);
    const float4* ad = (const float4*)(g_a_dst + (size_t)d * 8);
    float4 s0 = as[0], s1 = as[1];
    float4 d0 = ad[0], d1 = ad[1];

    float4 o0, o1;
    o0.x = fmaxf(a[0] + s0.x + d0.x, 0.f);
    o0.y = fmaxf(a[1] + s0.y + d0.y, 0.f);
    o0.z = fmaxf(a[2] + s0.z + d0.z, 0.f);
    o0.w = fmaxf(a[3] + s0.w + d0.w, 0.f);
    o1.x = fmaxf(a[4] + s1.x + d1.x, 0.f);
    o1.y = fmaxf(a[5] + s1.y + d1.y, 0.f);
    o1.z = fmaxf(a[6] + s1.z + d1.z, 0.f);
    o1.w = fmaxf(a[7] + s1.w + d1.w, 0.f);
    float4* op = (float4*)(g_att + (size_t)eid * 8);
    op[0] = o0; op[1] = o1;

    atomicAdd(&g_count[d], 1);
}

// ============================================================
// K3a: per-block exclusive scan of degree histogram
// ============================================================
__global__ __launch_bounds__(1024) void scan_local_kernel(int n) {
    __shared__ int ws[32];
    const int tid = threadIdx.x;
    const int i = blockIdx.x * 1024 + tid;
    int v = (i < n) ? g_count[i] : 0;

    int lane = tid & 31, w = tid >> 5;
    int x = v;
    #pragma unroll
    for (int s = 1; s < 32; s <<= 1) {
        int y = __shfl_up_sync(0xFFFFFFFFu, x, s);
        if (lane >= s) x += y;
    }
    if (lane == 31) ws[w] = x;
    __syncthreads();
    if (w == 0) {
        int y = ws[lane];
        #pragma unroll
        for (int s = 1; s < 32; s <<= 1) {
            int z = __shfl_up_sync(0xFFFFFFFFu, y, s);
            if (lane >= s) y += z;
        }
        ws[lane] = y;
    }
    __syncthreads();
    int incl = x + (w > 0 ? ws[w - 1] : 0);
    if (i < n) g_rowstart[i] = incl - v;          // block-local exclusive
    if (tid == 1023) g_blocksum[blockIdx.x] = incl;
}

// ============================================================
// K3b: scan of block sums (<=64 entries), single tiny block
// ============================================================
__global__ __launch_bounds__(64) void scan_sums_kernel(int nb, int n) {
    __shared__ int b[64];
    const int t = threadIdx.x;
    int v = (t < nb) ? g_blocksum[t] : 0;
    b[t] = v;
    __syncthreads();
    #pragma unroll
    for (int s = 1; s < 64; s <<= 1) {
        int add = (t >= s) ? b[t - s] : 0;
        __syncthreads();
        b[t] += add;
        __syncthreads();
    }
    g_blockoff[t] = b[t] - v;
    if (t == 63) g_rowstart[n] = b[63];
}

// ============================================================
// K3c: add block offsets, init cursors
// ============================================================
__global__ __launch_bounds__(1024) void scan_add_kernel(int n) {
    int i = blockIdx.x * 1024 + threadIdx.x;
    if (i < n) {
        int r = g_rowstart[i] + g_blockoff[blockIdx.x];
        g_rowstart[i] = r;
        g_cursor[i]   = r;
    }
}

// ============================================================
// K3d: scatter edge ids into CSR order
// ============================================================
__global__ void scatter_kernel(const int* __restrict__ dst, int e) {
    int i = blockIdx.x * blockDim.x + threadIdx.x;
    if (i < e) {
        int d = dst[i];
        int pos = atomicAdd(&g_cursor[d], 1);
        g_perm[pos] = i;
    }
}

// ============================================================
// K4: per-destination softmax + weighted aggregation.
// Stage edge ids + att rows in smem; compute each alpha once.
// ============================================================
__global__ __launch_bounds__(128) void aggregate_kernel(
    const int* __restrict__ src, float* __restrict__ out, int n)
{
    const int d = blockIdx.x;
    const int beg = g_rowstart[d];
    const int end = g_rowstart[d + 1];
    const int deg = end - beg;
    if (deg == 0) return;   // out already holds prop_dst

    __shared__ int   s_eid[CAP];
    __shared__ float s_att[CAP * 8];   // att rows, then overwritten with alpha
    __shared__ float s_m[8], s_inv[8];
    const int t = threadIdx.x;

    if (deg <= CAP) {
        // stage edge ids + source ids + att rows (coalesced-ish, once)
        for (int i = t; i < deg; i += 128) {
            int eid = g_perm[beg + i];
            s_eid[i] = src[eid];
            const float4* ap = (const float4*)(g_att + (size_t)eid * 8);
            ((float4*)s_att)[i * 2]     = ap[0];
            ((float4*)s_att)[i * 2 + 1] = ap[1];
        }
        __syncthreads();

        if (t < 8) {
            float m = 0.f;   // att >= 0 -> 0 is exact max identity
            for (int i = 0; i < deg; i++) m = fmaxf(m, s_att[i * 8 + t]);
            float ss = 0.f;
            for (int i = 0; i < deg; i++) ss += __expf(s_att[i * 8 + t] - m);
            s_m[t]   = m;
            s_inv[t] = 1.f / fmaxf(ss, 1e-16f);
        }
        __syncthreads();

        // alpha computed ONCE per (edge, head)
        for (int idx = t; idx < deg * 8; idx += 128) {
            int h = idx & 7;
            s_att[idx] = __expf(s_att[idx] - s_m[h]) * s_inv[h];
        }
        __syncthreads();

        const int h = t >> 4;
        float acc = 0.f;
        int i = 0;
        for (; i + 4 <= deg; i += 4) {
            int   e0 = s_eid[i],     e1 = s_eid[i + 1];
            int   e2 = s_eid[i + 2], e3 = s_eid[i + 3];
            float a0 = s_att[(i    ) * 8 + h], a1 = s_att[(i + 1) * 8 + h];
            float a2 = s_att[(i + 2) * 8 + h], a3 = s_att[(i + 3) * 8 + h];
            float p0 = g_prop_src[(size_t)e0 * 128 + t];
            float p1 = g_prop_src[(size_t)e1 * 128 + t];
            float p2 = g_prop_src[(size_t)e2 * 128 + t];
            float p3 = g_prop_src[(size_t)e3 * 128 + t];
            acc = fmaf(p0, a0, acc);
            acc = fmaf(p1, a1, acc);
            acc = fmaf(p2, a2, acc);
            acc = fmaf(p3, a3, acc);
        }
        for (; i < deg; i++)
            acc = fmaf(g_prop_src[(size_t)s_eid[i] * 128 + t], s_att[i * 8 + h], acc);
        out[(size_t)d * 128 + t] += acc;
    } else {
        // fallback (deg > CAP; effectively never for this graph)
        if (t < 8) {
            float m = 0.f;
            for (int i = beg; i < end; i++)
                m = fmaxf(m, g_att[(size_t)g_perm[i] * 8 + t]);
            float ss = 0.f;
            for (int i = beg; i < end; i++)
                ss += __expf(g_att[(size_t)g_perm[i] * 8 + t] - m);
            s_m[t]   = m;
            s_inv[t] = 1.f / fmaxf(ss, 1e-16f);
        }
        __syncthreads();
        const int h = t >> 4;
        const float m = s_m[h], inv = s_inv[h];
        float acc = 0.f;
        for (int i = beg; i < end; i++) {
            int eid = g_perm[i];
            float al = __expf(g_att[(size_t)eid * 8 + h] - m) * inv;
            acc = fmaf(g_prop_src[(size_t)src[eid] * 128 + t], al, acc);
        }
        out[(size_t)d * 128 + t] += acc;
    }
}

// ============================================================
// launch
// ============================================================
extern "C" void kernel_launch(void* const* d_in, const int* in_sizes, int n_in,
                              void* d_out, int out_size)
{
    const float* feat      = (const float*)d_in[0];
    const float* feat_edge = (const float*)d_in[1];
    const int*   src       = (const int*)  d_in[2];
    const int*   dst       = (const int*)  d_in[3];
    const float* was0      = (const float*)d_in[4];
    const float* was1      = (const float*)d_in[5];
    const float* wad0      = (const float*)d_in[6];
    const float* wad1      = (const float*)d_in[7];
    const float* we0       = (const float*)d_in[8];
    const float* we1       = (const float*)d_in[9];
    const float* wps       = (const float*)d_in[10];
    const float* bps       = (const float*)d_in[11];
    const float* wpd       = (const float*)d_in[12];
    const float* bpd       = (const float*)d_in[13];
    float* out = (float*)d_out;

    int n = in_sizes[0] / 128;
    int e = in_sizes[2];
    int nb = (n + 1023) / 1024;

    zero_count_kernel<<<(n + 256) / 256, 256>>>(n);
    node_kernel<<<(n + 31) / 32, 128>>>(feat, wps, bps, wpd, bpd,
                                        was0, was1, wad0, wad1, out, n);
    edge_att_kernel<<<(e + 255) / 256, 256>>>(feat_edge, src, dst, we0, we1, e);
    scan_local_kernel<<<nb, 1024>>>(n);
    scan_sums_kernel<<<1, 64>>>(nb, n);
    scan_add_kernel<<<nb, 1024>>>(n);
    scatter_kernel<<<(e + 255) / 256, 256>>>(dst, e);
    aggregate_kernel<<<n, 128>>>(src, out, n);
}

// round 5
// speedup vs baseline: 1.5371x; 1.0306x over previous
#include <cuda_runtime.h>
#include <cstdint>

#define MAXN 50000
#define MAXE 800000
#define CAP  64    // max staged edges per destination (Poisson(16): P(deg>64) ~ e^-126)

// -------- scratch (device globals; no allocation) --------
__device__ float g_prop_src[MAXN * 128];   // [N,128]
__device__ float g_a_src[MAXN * 8];        // [N,8]
__device__ float g_a_dst[MAXN * 8];        // [N,8]
__device__ float g_att_csr[MAXE * 8];      // att rows in CSR-by-dst order
__device__ int   g_srcid[MAXE];            // src node id in CSR-by-dst order
__device__ int   g_count[MAXN + 1];
__device__ int   g_rowstart[MAXN + 1];
__device__ int   g_cursor[MAXN];
__device__ int   g_blocksum[64];
__device__ int   g_blockoff[64];

// -------- f32x2 packed-FMA helpers (FFMA2; PTX-only) --------
__device__ __forceinline__ void ffma2(unsigned long long& d,
                                      unsigned long long a,
                                      unsigned long long b) {
    asm("fma.rn.f32x2 %0, %1, %2, %0;" : "+l"(d) : "l"(a), "l"(b));
}
__device__ __forceinline__ unsigned long long pack2(float x) {
    unsigned long long r;
    asm("mov.b64 %0, {%1, %1};" : "=l"(r) : "f"(x));
    return r;
}
__device__ __forceinline__ unsigned long long pack2two(float lo, float hi) {
    unsigned long long r;
    asm("mov.b64 %0, {%1, %2};" : "=l"(r) : "f"(lo), "f"(hi));
    return r;
}
__device__ __forceinline__ void unpack2(unsigned long long v, float& lo, float& hi) {
    asm("mov.b64 {%0, %1}, %2;" : "=f"(lo), "=f"(hi) : "l"(v));
}

// ============================================================
// K0: zero histogram
// ============================================================
__global__ void zero_count_kernel(int n) {
    int i = blockIdx.x * blockDim.x + threadIdx.x;
    if (i <= n) g_count[i] = 0;
}

// ============================================================
// K0b: degree histogram (dst only)
// ============================================================
__global__ void hist_kernel(const int* __restrict__ dst, int e) {
    int i = blockIdx.x * blockDim.x + threadIdx.x;
    if (i < e) atomicAdd(&g_count[dst[i]], 1);
}

// ============================================================
// K1: per-node GEMMs (FFMA2 + LDS.128).
// feat tile transposed: sft[k][i], pitch 36 floats (16B-aligned rows).
// ============================================================
__global__ __launch_bounds__(128) void node_kernel(
    const float* __restrict__ feat,
    const float* __restrict__ wps, const float* __restrict__ bps,
    const float* __restrict__ wpd, const float* __restrict__ bpd,
    const float* __restrict__ was0, const float* __restrict__ was1,
    const float* __restrict__ wad0, const float* __restrict__ wad1,
    float* __restrict__ out, int n)
{
    __shared__ __align__(16) float sft[128 * 36];  // [k][i]; later hidden [col][i]
    const int tid = threadIdx.x;
    const int n0 = blockIdx.x * 32;

    // load transposed feat tile: thread tid = feature k, iterate nodes
    #pragma unroll 4
    for (int i = 0; i < 32; i++) {
        int node = n0 + i;
        float v = (node < n) ? feat[(size_t)node * 128 + tid] : 0.f;
        sft[tid * 36 + i] = v;
    }
    __syncthreads();

    // ---- fused prop_src / prop_dst: thread = output column tid ----
    {
        unsigned long long acc1[16], acc2[16];
        #pragma unroll
        for (int j = 0; j < 16; j++) { acc1[j] = 0ull; acc2[j] = 0ull; }
        #pragma unroll 2
        for (int k = 0; k < 128; k++) {
            unsigned long long w1 = pack2(wps[k * 128 + tid]);
            unsigned long long w2 = pack2(wpd[k * 128 + tid]);
            const ulonglong2* fp = (const ulonglong2*)&sft[k * 36];
            #pragma unroll
            for (int j = 0; j < 8; j++) {
                ulonglong2 f = fp[j];
                ffma2(acc1[2 * j],     f.x, w1);
                ffma2(acc1[2 * j + 1], f.y, w1);
                ffma2(acc2[2 * j],     f.x, w2);
                ffma2(acc2[2 * j + 1], f.y, w2);
            }
        }
        float bs = bps[tid], bd = bpd[tid];
        #pragma unroll
        for (int j = 0; j < 16; j++) {
            float l1, h1, l2, h2;
            unpack2(acc1[j], l1, h1);
            unpack2(acc2[j], l2, h2);
            int na = n0 + 2 * j, nb = na + 1;
            if (na < n) {
                g_prop_src[(size_t)na * 128 + tid] = l1 + bs;
                out[(size_t)na * 128 + tid]        = l2 + bd;
            }
            if (nb < n) {
                g_prop_src[(size_t)nb * 128 + tid] = h1 + bs;
                out[(size_t)nb * 128 + tid]        = h2 + bd;
            }
        }
    }

    // ---- attention layer 0: threads 0..63 src cols, 64..127 dst cols ----
    {
        const float* W0 = (tid < 64) ? was0 : wad0;
        const int col = tid & 63;
        unsigned long long acc[16];
        #pragma unroll
        for (int j = 0; j < 16; j++) acc[j] = 0ull;
        #pragma unroll 2
        for (int k = 0; k < 128; k++) {
            unsigned long long w = pack2(W0[k * 64 + col]);
            const ulonglong2* fp = (const ulonglong2*)&sft[k * 36];
            #pragma unroll
            for (int j = 0; j < 8; j++) {
                ulonglong2 f = fp[j];
                ffma2(acc[2 * j],     f.x, w);
                ffma2(acc[2 * j + 1], f.y, w);
            }
        }
        __syncthreads();   // all reads of feat tile done
        #pragma unroll
        for (int j = 0; j < 16; j++) {
            float lo, hi;
            unpack2(acc[j], lo, hi);
            sft[tid * 36 + 2 * j]     = fmaxf(lo, 0.f);
            sft[tid * 36 + 2 * j + 1] = fmaxf(hi, 0.f);
        }
        __syncthreads();
    }

    // ---- attention layer 1: 32 nodes x (2 mats x 8 heads) = 512 outputs ----
    #pragma unroll
    for (int q = 0; q < 4; q++) {
        int o   = q * 128 + tid;
        int i   = o >> 4;
        int rem = o & 15;
        int mat = rem >> 3;
        int h   = rem & 7;
        const float* W1 = mat ? wad1 : was1;
        float s = 0.f;
        #pragma unroll
        for (int t = 0; t < 64; t++)
            s = fmaf(sft[(mat * 64 + t) * 36 + i], W1[t * 8 + h], s);
        int node = n0 + i;
        if (node < n) {
            if (mat == 0) g_a_src[node * 8 + h] = s;
            else          g_a_dst[node * 8 + h] = s;
        }
    }
}

// ============================================================
// K2: per-edge attention logits (FFMA2 inner) + CSR scatter.
// Writes att row and src id directly at the CSR position.
// ============================================================
__global__ __launch_bounds__(256) void edge_att_kernel(
    const float* __restrict__ feat_edge,
    const int* __restrict__ src, const int* __restrict__ dst,
    const float* __restrict__ we0, const float* __restrict__ we1,
    int e)
{
    __shared__ __align__(8) unsigned long long sw0p[8 * 32];  // [k][tp]: (w[k][2tp], w[k][2tp+1])
    __shared__ __align__(8) unsigned long long sw1p[32 * 8];  // [tp][h]: (w1[2tp][h], w1[2tp+1][h])
    const int tid = threadIdx.x;
    for (int i = tid; i < 256; i += 256) {
        int k = i >> 5, tp = i & 31;
        sw0p[i] = pack2two(we0[k * 64 + 2 * tp], we0[k * 64 + 2 * tp + 1]);
    }
    for (int i = tid; i < 256; i += 256) {
        int tp = i >> 3, h = i & 7;
        sw1p[i] = pack2two(we1[(2 * tp) * 8 + h], we1[(2 * tp + 1) * 8 + h]);
    }
    __syncthreads();

    int eid = blockIdx.x * 256 + tid;
    if (eid >= e) return;

    unsigned long long fe2[8];
    {
        const float4* fp = (const float4*)(feat_edge + (size_t)eid * 8);
        float4 f0 = fp[0], f1 = fp[1];
        fe2[0] = pack2(f0.x); fe2[1] = pack2(f0.y);
        fe2[2] = pack2(f0.z); fe2[3] = pack2(f0.w);
        fe2[4] = pack2(f1.x); fe2[5] = pack2(f1.y);
        fe2[6] = pack2(f1.z); fe2[7] = pack2(f1.w);
    }

    unsigned long long acc2[8];
    #pragma unroll
    for (int h = 0; h < 8; h++) acc2[h] = 0ull;

    #pragma unroll 4
    for (int tp = 0; tp < 32; tp++) {
        unsigned long long hv2 = 0ull;
        #pragma unroll
        for (int k = 0; k < 8; k++) ffma2(hv2, fe2[k], sw0p[k * 32 + tp]);
        float lo, hi;
        unpack2(hv2, lo, hi);
        hv2 = pack2two(fmaxf(lo, 0.f), fmaxf(hi, 0.f));
        #pragma unroll
        for (int h = 0; h < 8; h++) ffma2(acc2[h], hv2, sw1p[tp * 8 + h]);
    }

    float a[8];
    #pragma unroll
    for (int h = 0; h < 8; h++) {
        float lo, hi;
        unpack2(acc2[h], lo, hi);
        a[h] = lo + hi;
    }

    int s = src[eid], d = dst[eid];
    const float4* as = (const float4*)(g_a_src + (size_t)s * 8);
    const float4* ad = (const float4*)(g_a_dst + (size_t)d * 8);
    float4 s0 = as[0], s1 = as[1];
    float4 d0 = ad[0], d1 = ad[1];

    float4 o0, o1;
    o0.x = fmaxf(a[0] + s0.x + d0.x, 0.f);
    o0.y = fmaxf(a[1] + s0.y + d0.y, 0.f);
    o0.z = fmaxf(a[2] + s0.z + d0.z, 0.f);
    o0.w = fmaxf(a[3] + s0.w + d0.w, 0.f);
    o1.x = fmaxf(a[4] + s1.x + d1.x, 0.f);
    o1.y = fmaxf(a[5] + s1.y + d1.y, 0.f);
    o1.z = fmaxf(a[6] + s1.z + d1.z, 0.f);
    o1.w = fmaxf(a[7] + s1.w + d1.w, 0.f);

    int pos = atomicAdd(&g_cursor[d], 1);
    float4* op = (float4*)(g_att_csr + (size_t)pos * 8);
    op[0] = o0; op[1] = o1;
    g_srcid[pos] = s;
}

// ============================================================
// K3a/b/c: parallel exclusive scan of degree histogram
// ============================================================
__global__ __launch_bounds__(1024) void scan_local_kernel(int n) {
    __shared__ int ws[32];
    const int tid = threadIdx.x;
    const int i = blockIdx.x * 1024 + tid;
    int v = (i < n) ? g_count[i] : 0;

    int lane = tid & 31, w = tid >> 5;
    int x = v;
    #pragma unroll
    for (int s = 1; s < 32; s <<= 1) {
        int y = __shfl_up_sync(0xFFFFFFFFu, x, s);
        if (lane >= s) x += y;
    }
    if (lane == 31) ws[w] = x;
    __syncthreads();
    if (w == 0) {
        int y = ws[lane];
        #pragma unroll
        for (int s = 1; s < 32; s <<= 1) {
            int z = __shfl_up_sync(0xFFFFFFFFu, y, s);
            if (lane >= s) y += z;
        }
        ws[lane] = y;
    }
    __syncthreads();
    int incl = x + (w > 0 ? ws[w - 1] : 0);
    if (i < n) g_rowstart[i] = incl - v;
    if (tid == 1023) g_blocksum[blockIdx.x] = incl;
}

__global__ __launch_bounds__(64) void scan_sums_kernel(int nb, int n) {
    __shared__ int b[64];
    const int t = threadIdx.x;
    int v = (t < nb) ? g_blocksum[t] : 0;
    b[t] = v;
    __syncthreads();
    #pragma unroll
    for (int s = 1; s < 64; s <<= 1) {
        int add = (t >= s) ? b[t - s] : 0;
        __syncthreads();
        b[t] += add;
        __syncthreads();
    }
    g_blockoff[t] = b[t] - v;
    if (t == 63) g_rowstart[n] = b[63];
}

__global__ __launch_bounds__(1024) void scan_add_kernel(int n) {
    int i = blockIdx.x * 1024 + threadIdx.x;
    if (i < n) {
        int r = g_rowstart[i] + g_blockoff[blockIdx.x];
        g_rowstart[i] = r;
        g_cursor[i]   = r;
    }
}

// ============================================================
// K4: per-destination softmax + weighted aggregation.
// CSR-ordered att/src -> coalesced staging; tiny smem footprint.
// ============================================================
__global__ __launch_bounds__(128) void aggregate_kernel(
    float* __restrict__ out, int n)
{
    const int d = blockIdx.x;
    const int beg = g_rowstart[d];
    const int end = g_rowstart[d + 1];
    const int deg = end - beg;
    if (deg == 0) return;   // out already holds prop_dst

    __shared__ int   s_src[CAP];
    __shared__ float s_att[CAP * 8];
    __shared__ float s_m[8], s_inv[8];
    const int t = threadIdx.x;

    if (deg <= CAP) {
        // stage src ids + att rows (fully coalesced: CSR-contiguous)
        for (int i = t; i < deg; i += 128) s_src[i] = g_srcid[beg + i];
        for (int i = t; i < deg * 2; i += 128)
            ((float4*)s_att)[i] = ((const float4*)(g_att_csr + (size_t)beg * 8))[i];
        __syncthreads();

        if (t < 8) {
            float m = 0.f;   // att >= 0 -> 0 is exact max identity
            for (int i = 0; i < deg; i++) m = fmaxf(m, s_att[i * 8 + t]);
            float ss = 0.f;
            for (int i = 0; i < deg; i++) ss += __expf(s_att[i * 8 + t] - m);
            s_m[t]   = m;
            s_inv[t] = 1.f / fmaxf(ss, 1e-16f);
        }
        __syncthreads();

        // alpha computed once per (edge, head)
        for (int idx = t; idx < deg * 8; idx += 128) {
            int h = idx & 7;
            s_att[idx] = __expf(s_att[idx] - s_m[h]) * s_inv[h];
        }
        __syncthreads();

        const int h = t >> 4;
        float acc = 0.f;
        int i = 0;
        for (; i + 4 <= deg; i += 4) {
            int   e0 = s_src[i],     e1 = s_src[i + 1];
            int   e2 = s_src[i + 2], e3 = s_src[i + 3];
            float a0 = s_att[(i    ) * 8 + h], a1 = s_att[(i + 1) * 8 + h];
            float a2 = s_att[(i + 2) * 8 + h], a3 = s_att[(i + 3) * 8 + h];
            float p0 = g_prop_src[(size_t)e0 * 128 + t];
            float p1 = g_prop_src[(size_t)e1 * 128 + t];
            float p2 = g_prop_src[(size_t)e2 * 128 + t];
            float p3 = g_prop_src[(size_t)e3 * 128 + t];
            acc = fmaf(p0, a0, acc);
            acc = fmaf(p1, a1, acc);
            acc = fmaf(p2, a2, acc);
            acc = fmaf(p3, a3, acc);
        }
        for (; i < deg; i++)
            acc = fmaf(g_prop_src[(size_t)s_src[i] * 128 + t], s_att[i * 8 + h], acc);
        out[(size_t)d * 128 + t] += acc;
    } else {
        // fallback: direct gmem (CSR order, still coalesced-ish)
        if (t < 8) {
            float m = 0.f;
            for (int i = beg; i < end; i++)
                m = fmaxf(m, g_att_csr[(size_t)i * 8 + t]);
            float ss = 0.f;
            for (int i = beg; i < end; i++)
                ss += __expf(g_att_csr[(size_t)i * 8 + t] - m);
            s_m[t]   = m;
            s_inv[t] = 1.f / fmaxf(ss, 1e-16f);
        }
        __syncthreads();
        const int h = t >> 4;
        const float m = s_m[h], inv = s_inv[h];
        float acc = 0.f;
        for (int i = beg; i < end; i++) {
            float al = __expf(g_att_csr[(size_t)i * 8 + h] - m) * inv;
            acc = fmaf(g_prop_src[(size_t)g_srcid[i] * 128 + t], al, acc);
        }
        out[(size_t)d * 128 + t] += acc;
    }
}

// ============================================================
// launch (node_kernel in profile slot 4)
// ============================================================
extern "C" void kernel_launch(void* const* d_in, const int* in_sizes, int n_in,
                              void* d_out, int out_size)
{
    const float* feat      = (const float*)d_in[0];
    const float* feat_edge = (const float*)d_in[1];
    const int*   src       = (const int*)  d_in[2];
    const int*   dst       = (const int*)  d_in[3];
    const float* was0      = (const float*)d_in[4];
    const float* was1      = (const float*)d_in[5];
    const float* wad0      = (const float*)d_in[6];
    const float* wad1      = (const float*)d_in[7];
    const float* we0       = (const float*)d_in[8];
    const float* we1       = (const float*)d_in[9];
    const float* wps       = (const float*)d_in[10];
    const float* bps       = (const float*)d_in[11];
    const float* wpd       = (const float*)d_in[12];
    const float* bpd       = (const float*)d_in[13];
    float* out = (float*)d_out;

    int n = in_sizes[0] / 128;
    int e = in_sizes[2];
    int nb = (n + 1023) / 1024;

    zero_count_kernel<<<(n + 256) / 256, 256>>>(n);
    hist_kernel<<<(e + 255) / 256, 256>>>(dst, e);
    scan_local_kernel<<<nb, 1024>>>(n);
    node_kernel<<<(n + 31) / 32, 128>>>(feat, wps, bps, wpd, bpd,
                                        was0, was1, wad0, wad1, out, n);
    scan_sums_kernel<<<1, 64>>>(nb, n);
    scan_add_kernel<<<nb, 1024>>>(n);
    edge_att_kernel<<<(e + 255) / 256, 256>>>(feat_edge, src, dst, we0, we1, e);
    aggregate_kernel<<<n, 128>>>(out, n);
}